// round 15
// baseline (speedup 1.0000x reference)
#include <cuda_runtime.h>
#include <cuda_bf16.h>
#include <cstdint>

#define NN    50000
#define EE    800000
#define NODE_D 128
#define EDGE_D 16
#define HID   300
#define H0W   150           // HID/2 bf16x2 words per row

#define NPAD  384
#define K1PAD 192           // GEMM1 K=144
#define K2PAD 320           // GEMM2 K=300

typedef unsigned long long u64;

// ---------------- scratch (device globals; no allocs allowed) ----------------
__device__ float g_inc[NN * EDGE_D + 64];
__device__ float g_agg[(size_t)NN * HID + 64];
__device__ float g_h0[(size_t)NN * HID + 64];
__device__ uint32_t g_h0bf[(size_t)NN * H0W + 64];   // bf16x2-packed h0 (30MB)
__device__ int   g_cnt[NN];
__device__ int   g_rowptr[NN];
__device__ int   g_cursor[NN];
__device__ int4  g_edges[EE];              // packed (src, eid, w_bits, 0)
__device__ __nv_bfloat16 g_w0t_hi[NPAD * K1PAD];
__device__ __nv_bfloat16 g_w0t_lo[NPAD * K1PAD];
__device__ __nv_bfloat16 g_wt_hi[NPAD * K2PAD];
__device__ __nv_bfloat16 g_wt_lo[NPAD * K2PAD];

// ---------------- asm helpers ----------------
__device__ __forceinline__ uint32_t smem_u32(const void* p) {
    return (uint32_t)__cvta_generic_to_shared(p);
}
__device__ __forceinline__ void ldsm_x4(uint32_t* r, uint32_t addr) {
    asm volatile("ldmatrix.sync.aligned.m8n8.x4.shared.b16 {%0,%1,%2,%3}, [%4];"
                 : "=r"(r[0]), "=r"(r[1]), "=r"(r[2]), "=r"(r[3]) : "r"(addr));
}
__device__ __forceinline__ void mma_bf16(float* d, const uint32_t* a, const uint32_t* b) {
    asm volatile(
        "mma.sync.aligned.m16n8k16.row.col.f32.bf16.bf16.f32 "
        "{%0,%1,%2,%3}, {%4,%5,%6,%7}, {%8,%9}, {%0,%1,%2,%3};"
        : "+f"(d[0]), "+f"(d[1]), "+f"(d[2]), "+f"(d[3])
        : "r"(a[0]), "r"(a[1]), "r"(a[2]), "r"(a[3]), "r"(b[0]), "r"(b[1]));
}
__device__ __forceinline__ void cp_async16(uint32_t dst, const void* src) {
    asm volatile("cp.async.cg.shared.global [%0], [%1], 16;" :: "r"(dst), "l"(src));
}
__device__ __forceinline__ void cp_commit() {
    asm volatile("cp.async.commit_group;" ::: "memory");
}
__device__ __forceinline__ void cp_wait0() {
    asm volatile("cp.async.wait_group 0;" ::: "memory");
}

// ---------------- kernel 1: zero cnt ----------------
__global__ void zero_kernel(int* __restrict__ cnt) {
    int i = blockIdx.x * blockDim.x + threadIdx.x;
    if (i < NN) cnt[i] = 0;
}

// ---------------- kernel 2: dst histogram ----------------
__global__ void hist_kernel(const int* __restrict__ edge_index, int* __restrict__ cnt) {
    int e = blockIdx.x * blockDim.x + threadIdx.x;
    if (e < EE) atomicAdd(&cnt[edge_index[EE + e]], 1);
}

// ---------------- kernel 3: single-block exclusive scan ----------------
__global__ void scan_kernel(const int* __restrict__ cnt,
                            int* __restrict__ rowptr,
                            int* __restrict__ cursor) {
    __shared__ int part[1024];
    const int n = NN;
    int t = threadIdx.x;
    const int chunk = (n + 1023) / 1024;
    int beg = t * chunk;
    int end = beg + chunk;
    if (beg > n) beg = n;
    if (end > n) end = n;
    int s = 0;
    for (int i = beg; i < end; i++) s += cnt[i];
    part[t] = s;
    __syncthreads();
    for (int off = 1; off < 1024; off <<= 1) {
        int v = (t >= off) ? part[t - off] : 0;
        __syncthreads();
        part[t] += v;
        __syncthreads();
    }
    int run = part[t] - s;
    for (int i = beg; i < end; i++) {
        rowptr[i] = run;
        cursor[i] = run;
        run += cnt[i];
    }
}

// ---------------- kernel 4: bucket edges by dst (packed int4) ----------------
__global__ void fill_kernel(const float* __restrict__ edge_weight,
                            const int* __restrict__ edge_index,
                            int* __restrict__ cursor,
                            int4* __restrict__ edges) {
    int e = blockIdx.x * blockDim.x + threadIdx.x;
    if (e >= EE) return;
    int src = edge_index[e];
    int dst = edge_index[EE + e];
    int pos = atomicAdd(&cursor[dst], 1);
    edges[pos] = make_int4(src, e, __float_as_int(edge_weight[e]), 0);
}

// ---------------- kernel 5: inc via CSR gather (no atomics) ------------------
__global__ __launch_bounds__(256)
void inc_csr_kernel(const float* __restrict__ edge_attr,
                    const int* __restrict__ rowptr,
                    const int* __restrict__ cnt_arr,
                    const int4* __restrict__ edges,
                    float* __restrict__ inc) {
    int node = blockIdx.x * 8 + (threadIdx.x >> 5);
    if (node >= NN) return;
    int lane = threadIdx.x & 31;
    int start = rowptr[node];
    int cnt = cnt_arr[node];
    int d = lane & 15;
    int half = lane >> 4;
    float acc = 0.f;
    for (int j = half; j < cnt; j += 2) {
        int4 ed = edges[start + j];
        float w = __int_as_float(ed.z);
        acc += w * edge_attr[ed.y * EDGE_D + d];
    }
    acc += __shfl_xor_sync(0xffffffffu, acc, 16);
    if (half == 0) inc[node * EDGE_D + d] = acc;
}

// ------------- weight prep: transpose + bf16 split + zero-pad ---------------
__global__ void prep_weight(const float* __restrict__ src,
                            __nv_bfloat16* __restrict__ hi,
                            __nv_bfloat16* __restrict__ lo,
                            int K, int Nn, int KPAD) {
    int idx = blockIdx.x * blockDim.x + threadIdx.x;
    if (idx >= NPAD * KPAD) return;
    int n = idx / KPAD;
    int k = idx - n * KPAD;
    float v = (k < K && n < Nn) ? src[(size_t)k * Nn + n] : 0.f;
    __nv_bfloat16 h = __float2bfloat16(v);
    float r = v - __bfloat162float(h);
    hi[idx] = h;
    lo[idx] = __float2bfloat16(r);
}

// ------------- h0 -> bf16x2 repack (fully coalesced streaming) ---------------
__global__ void pack_h0_kernel(const float* __restrict__ h0,
                               uint32_t* __restrict__ h0bf) {
    size_t idx = (size_t)blockIdx.x * blockDim.x + threadIdx.x;
    if (idx >= (size_t)NN * H0W) return;
    float2 v = *reinterpret_cast<const float2*>(h0 + 2 * idx);
    __nv_bfloat162 bw = __float22bfloat162_rn(v);
    h0bf[idx] = *reinterpret_cast<uint32_t*>(&bw);
}

// ---------------- split-bf16 HMMA GEMM, half-chunk pipelined -----------------
#define HSTR 40                          // 32 k + 8 pad (80B row stride)
#define TILEH (128 * HSTR)
#define BUFSET (4 * TILEH)
#define GEMM_SMEM (2 * BUFSET * 2)       // 81920 B

template<int JPMAX>
__device__ __forceinline__ void mma_phase(
    float (&acc)[2][8][4],
    const __nv_bfloat16* Ah, const __nv_bfloat16* Al,
    const __nv_bfloat16* Bh, const __nv_bfloat16* Bl,
    int ksteps, int warp_m, int warp_n,
    int a_row_l, int a_kh, int b_mat, int b_rr)
{
    for (int ks = 0; ks < ksteps; ks++) {
        int k0 = ks * 16;
        uint32_t ah[2][4], al[2][4];
#pragma unroll
        for (int i = 0; i < 2; i++) {
            int arow = warp_m * 32 + i * 16 + a_row_l;
            ldsm_x4(ah[i], smem_u32(Ah + arow * HSTR + k0 + a_kh));
            ldsm_x4(al[i], smem_u32(Al + arow * HSTR + k0 + a_kh));
        }
#pragma unroll
        for (int jp = 0; jp < JPMAX; jp++) {
            int brow = warp_n * 64 + (jp * 2 + (b_mat >> 1)) * 8 + b_rr;
            int bk   = k0 + (b_mat & 1) * 8;
            uint32_t bh[4], bl[4];
            ldsm_x4(bh, smem_u32(Bh + brow * HSTR + bk));
            ldsm_x4(bl, smem_u32(Bl + brow * HSTR + bk));
#pragma unroll
            for (int i = 0; i < 2; i++) {
                mma_bf16(acc[i][2*jp],   ah[i], &bh[0]);
                mma_bf16(acc[i][2*jp],   al[i], &bh[0]);
                mma_bf16(acc[i][2*jp],   ah[i], &bl[0]);
                mma_bf16(acc[i][2*jp+1], ah[i], &bh[2]);
                mma_bf16(acc[i][2*jp+1], al[i], &bh[2]);
                mma_bf16(acc[i][2*jp+1], ah[i], &bl[2]);
            }
        }
    }
}

template<bool CONCAT>
__device__ __forceinline__ void load_A_regs(
    float (&va)[2][8], const float* __restrict__ A, const float* __restrict__ A2,
    int m0, int khbase, int M, int K, int K1, int tid)
{
#pragma unroll
    for (int it = 0; it < 2; it++) {
        int idx = tid + it * 256;
        int row = idx >> 2, grp = idx & 3;
        int gm = m0 + row;
        int gk = khbase + grp * 8;
        if (gm < M && gk + 8 <= K) {
            const float* p;
            if (CONCAT) p = (gk < K1) ? (A + (size_t)gm * K1 + gk)
                                      : (A2 + (size_t)gm * (K - K1) + (gk - K1));
            else        p = A + (size_t)gm * K + gk;
            float4 u0 = *reinterpret_cast<const float4*>(p);
            float4 u1 = *reinterpret_cast<const float4*>(p + 4);
            va[it][0]=u0.x; va[it][1]=u0.y; va[it][2]=u0.z; va[it][3]=u0.w;
            va[it][4]=u1.x; va[it][5]=u1.y; va[it][6]=u1.z; va[it][7]=u1.w;
        } else {
#pragma unroll
            for (int i = 0; i < 8; i++) {
                int kk = gk + i;
                float val = 0.f;
                if (gm < M && kk < K) {
                    if (CONCAT) val = (kk < K1) ? A[(size_t)gm * K1 + kk]
                                                : A2[(size_t)gm * (K - K1) + (kk - K1)];
                    else        val = A[(size_t)gm * K + kk];
                }
                va[it][i] = val;
            }
        }
    }
}

__device__ __forceinline__ void store_A_split(
    const float (&va)[2][8], __nv_bfloat16* Ah, __nv_bfloat16* Al, int tid)
{
#pragma unroll
    for (int it = 0; it < 2; it++) {
        int idx = tid + it * 256;
        int row = idx >> 2, grp = idx & 3;
        uint32_t hw[4], lw[4];
#pragma unroll
        for (int i = 0; i < 4; i++) {
            float v0 = va[it][2*i], v1 = va[it][2*i+1];
            __nv_bfloat16 h0b = __float2bfloat16(v0);
            __nv_bfloat16 h1b = __float2bfloat16(v1);
            __nv_bfloat16 l0b = __float2bfloat16(v0 - __bfloat162float(h0b));
            __nv_bfloat16 l1b = __float2bfloat16(v1 - __bfloat162float(h1b));
            hw[i] = (uint32_t)__bfloat16_as_ushort(h0b) | ((uint32_t)__bfloat16_as_ushort(h1b) << 16);
            lw[i] = (uint32_t)__bfloat16_as_ushort(l0b) | ((uint32_t)__bfloat16_as_ushort(l1b) << 16);
        }
        int off = row * HSTR + grp * 8;
        *reinterpret_cast<uint4*>(Ah + off) = make_uint4(hw[0], hw[1], hw[2], hw[3]);
        *reinterpret_cast<uint4*>(Al + off) = make_uint4(lw[0], lw[1], lw[2], lw[3]);
    }
}

__device__ __forceinline__ void fill_B_async(
    const __nv_bfloat16* __restrict__ Bhi, const __nv_bfloat16* __restrict__ Blo,
    __nv_bfloat16* Bh, __nv_bfloat16* Bl, int n0, int khbase, int KPAD, int tid)
{
#pragma unroll
    for (int it = 0; it < 2; it++) {
        int idx = tid + it * 256;
        int row = idx >> 2, grp = idx & 3;
        size_t gidx = (size_t)(n0 + row) * KPAD + khbase + grp * 8;
        int off = row * HSTR + grp * 8;
        cp_async16(smem_u32(Bh + off), Bhi + gidx);
        cp_async16(smem_u32(Bl + off), Blo + gidx);
    }
}

template<bool CONCAT, bool RESID>
__global__ __launch_bounds__(256, 2)
void gemm_hmma(const float* __restrict__ A, const float* __restrict__ A2,
               const __nv_bfloat16* __restrict__ Bhi, const __nv_bfloat16* __restrict__ Blo,
               const float* __restrict__ bias, const float* __restrict__ resid,
               float* __restrict__ C, int M, int Nn, int K, int K1, int KPAD) {
    extern __shared__ __nv_bfloat16 sm[];

    int tid = threadIdx.x;
    int wid = tid >> 5, lid = tid & 31;
    int warp_m = wid >> 1;          // 0..3
    int warp_n = wid & 1;           // 0..1
    int m0 = blockIdx.y * 128;
    int n0 = blockIdx.x * 128;

    int jp_max = 4;
    {
        int cols_needed = Nn - (n0 + warp_n * 64);
        if (cols_needed <= 0) jp_max = 0;
        else if (cols_needed < 64) jp_max = (cols_needed + 15) >> 4;
    }

    float acc[2][8][4];
#pragma unroll
    for (int i = 0; i < 2; i++)
#pragma unroll
        for (int j = 0; j < 8; j++)
#pragma unroll
            for (int q = 0; q < 4; q++) acc[i][j][q] = 0.f;

    int a_row_l = lid & 15;
    int a_kh    = (lid >> 4) * 8;
    int b_mat   = lid >> 3;
    int b_rr    = lid & 7;

    const int nhalf = (K + 31) >> 5;
    float va[2][8];

    // ---- prologue: fill half 0 ----
    fill_B_async(Bhi, Blo, sm + 2 * TILEH, sm + 3 * TILEH, n0, 0, KPAD, tid);
    cp_commit();
    load_A_regs<CONCAT>(va, A, A2, m0, 0, M, K, K1, tid);
    store_A_split(va, sm, sm + TILEH, tid);
    cp_wait0();
    __syncthreads();

    for (int h = 0; h < nhalf; h++) {
        __nv_bfloat16* cur = sm + (h & 1) * BUFSET;
        __nv_bfloat16* nxt = sm + ((h + 1) & 1) * BUFSET;
        bool pf = (h + 1 < nhalf);
        if (pf) {
            fill_B_async(Bhi, Blo, nxt + 2 * TILEH, nxt + 3 * TILEH,
                         n0, (h + 1) << 5, KPAD, tid);
            cp_commit();
            load_A_regs<CONCAT>(va, A, A2, m0, (h + 1) << 5, M, K, K1, tid);
        }

        int rem = K - (h << 5);
        int ksteps = (rem + 15) >> 4;
        if (ksteps > 2) ksteps = 2;
        if (jp_max == 4)
            mma_phase<4>(acc, cur, cur + TILEH, cur + 2 * TILEH, cur + 3 * TILEH,
                         ksteps, warp_m, warp_n, a_row_l, a_kh, b_mat, b_rr);
        else if (jp_max == 3)
            mma_phase<3>(acc, cur, cur + TILEH, cur + 2 * TILEH, cur + 3 * TILEH,
                         ksteps, warp_m, warp_n, a_row_l, a_kh, b_mat, b_rr);

        if (pf) {
            store_A_split(va, nxt, nxt + TILEH, tid);
            cp_wait0();
        }
        __syncthreads();
    }

    // ---- epilogue: bias (+resid) + relu ----
    int tq = lid >> 2;
    int tr = lid & 3;
    int row_base = m0 + warp_m * 32 + tq;
    int col_base = n0 + warp_n * 64 + tr * 2;
#pragma unroll
    for (int i = 0; i < 2; i++) {
#pragma unroll
        for (int j = 0; j < 8; j++) {
            int col = col_base + j * 8;
            if (col >= Nn) continue;
            float2 bs = *reinterpret_cast<const float2*>(bias + col);
#pragma unroll
            for (int half = 0; half < 2; half++) {
                int row = row_base + i * 16 + half * 8;
                if (row >= M) continue;
                float v0 = acc[i][j][2*half + 0] + bs.x;
                float v1 = acc[i][j][2*half + 1] + bs.y;
                if (RESID) {
                    float2 rr = *reinterpret_cast<const float2*>(resid + (size_t)row * Nn + col);
                    v0 += rr.x; v1 += rr.y;
                }
                float2 o;
                o.x = fmaxf(v0, 0.f);
                o.y = fmaxf(v1, 0.f);
                *reinterpret_cast<float2*>(C + (size_t)row * Nn + col) = o;
            }
        }
    }
}

// ---------------- per-node CSR aggregation (bf16 gather, fp32 acc) -----------
__global__ __launch_bounds__(160)
void aggregate_kernel(const uint32_t* __restrict__ h0bf,
                      const int* __restrict__ rowptr,
                      const int* __restrict__ cnt_arr,
                      const int4* __restrict__ edges,
                      float* __restrict__ agg) {
    int i = blockIdx.x;
    int t = threadIdx.x;
    int start = rowptr[i];
    int cnt = cnt_arr[i];
    __shared__ int s_src[128];
    __shared__ float s_w[128];
    float a0 = 0.f, a1 = 0.f;
    for (int base = 0; base < cnt; base += 128) {
        int m = cnt - base; if (m > 128) m = 128;
        if (t < m) {
            int4 ed = edges[start + base + t];
            s_src[t] = ed.x;
            s_w[t]   = __int_as_float(ed.z);
        }
        __syncthreads();
        if (t < H0W) {
            for (int j = 0; j < m; j++) {
                uint32_t wv = h0bf[(size_t)s_src[j] * H0W + t];
                __nv_bfloat162 bv = *reinterpret_cast<__nv_bfloat162*>(&wv);
                float w = s_w[j];
                a0 += w * __bfloat162float(bv.x);
                a1 += w * __bfloat162float(bv.y);
            }
        }
        __syncthreads();
    }
    if (t < H0W) {
        float inv = 1.0f / fmaxf((float)cnt, 1.0f);
        float2 o = make_float2(a0 * inv, a1 * inv);
        *reinterpret_cast<float2*>(agg + (size_t)i * HID + 2 * t) = o;
    }
}

// ---------------- launch ----------------
extern "C" void kernel_launch(void* const* d_in, const int* in_sizes, int n_in,
                              void* d_out, int out_size) {
    const float* x = nullptr;
    const float* edge_attr = nullptr;
    const float* edge_weight = nullptr;
    const float* W0 = nullptr;
    const float* b0 = nullptr;
    const float* W  = nullptr;
    const float* b  = nullptr;
    const int*   edge_index = nullptr;

    for (int i = 0; i < n_in; i++) {
        int s = in_sizes[i];
        switch (s) {
            case NN * NODE_D:      x = (const float*)d_in[i]; break;
            case EE * EDGE_D:      edge_attr = (const float*)d_in[i]; break;
            case EE:               edge_weight = (const float*)d_in[i]; break;
            case (NODE_D + EDGE_D) * HID: W0 = (const float*)d_in[i]; break;
            case HID * HID:        W = (const float*)d_in[i]; break;
            case 2 * EE:           edge_index = (const int*)d_in[i]; break;
            case HID:
                if (!b0) b0 = (const float*)d_in[i];
                else     b  = (const float*)d_in[i];
                break;
            default: break; // node_weight unused
        }
    }
    if (!b) b = b0;

    void *p_inc, *p_agg, *p_h0, *p_h0bf, *p_cnt, *p_rowptr, *p_cursor, *p_edges;
    void *p_w0h, *p_w0l, *p_wh, *p_wl;
    cudaGetSymbolAddress(&p_inc,    g_inc);
    cudaGetSymbolAddress(&p_agg,    g_agg);
    cudaGetSymbolAddress(&p_h0,     g_h0);
    cudaGetSymbolAddress(&p_h0bf,   g_h0bf);
    cudaGetSymbolAddress(&p_cnt,    g_cnt);
    cudaGetSymbolAddress(&p_rowptr, g_rowptr);
    cudaGetSymbolAddress(&p_cursor, g_cursor);
    cudaGetSymbolAddress(&p_edges,  g_edges);
    cudaGetSymbolAddress(&p_w0h,    g_w0t_hi);
    cudaGetSymbolAddress(&p_w0l,    g_w0t_lo);
    cudaGetSymbolAddress(&p_wh,     g_wt_hi);
    cudaGetSymbolAddress(&p_wl,     g_wt_lo);

    float*    inc    = (float*)p_inc;
    float*    agg    = (float*)p_agg;
    uint32_t* h0bf   = (uint32_t*)p_h0bf;
    int*      cnt    = (int*)p_cnt;
    int*      rowptr = (int*)p_rowptr;
    int*      cursor = (int*)p_cursor;
    int4*     edges  = (int4*)p_edges;

    float* h = (float*)d_out;
    float* h0 = (out_size >= 2 * NN * HID) ? (float*)d_out + (size_t)NN * HID
                                           : (float*)p_h0;

    cudaFuncSetAttribute(gemm_hmma<true,  false>,
                         cudaFuncAttributeMaxDynamicSharedMemorySize, GEMM_SMEM);
    cudaFuncSetAttribute(gemm_hmma<false, true>,
                         cudaFuncAttributeMaxDynamicSharedMemorySize, GEMM_SMEM);

    // 1. zero cnt
    zero_kernel<<<(NN + 255) / 256, 256>>>(cnt);

    // 2. dst histogram
    hist_kernel<<<(EE + 255) / 256, 256>>>(edge_index, cnt);

    // 3. scan -> rowptr/cursor
    scan_kernel<<<1, 1024>>>(cnt, rowptr, cursor);

    // 4. bucket edges (packed)
    fill_kernel<<<(EE + 255) / 256, 256>>>(edge_weight, edge_index, cursor, edges);

    // 5. inc via CSR gather (no atomics)
    inc_csr_kernel<<<(NN + 7) / 8, 256>>>(edge_attr, rowptr, cnt, edges, inc);

    // 5b. weight prep
    prep_weight<<<(NPAD * K1PAD + 255) / 256, 256>>>(W0, (__nv_bfloat16*)p_w0h,
                                                     (__nv_bfloat16*)p_w0l,
                                                     NODE_D + EDGE_D, HID, K1PAD);
    prep_weight<<<(NPAD * K2PAD + 255) / 256, 256>>>(W, (__nv_bfloat16*)p_wh,
                                                     (__nv_bfloat16*)p_wl,
                                                     HID, HID, K2PAD);

    // 6. GEMM1: h0 = relu([x | inc] @ W0 + b0)
    {
        dim3 grid(NPAD / 128, (NN + 127) / 128);
        gemm_hmma<true, false><<<grid, 256, GEMM_SMEM>>>(
            x, inc, (__nv_bfloat16*)p_w0h, (__nv_bfloat16*)p_w0l,
            b0, nullptr, h0, NN, HID, NODE_D + EDGE_D, NODE_D, K1PAD);
    }

    // 6b. repack h0 -> bf16x2 (coalesced streaming)
    {
        size_t total = (size_t)NN * H0W;
        pack_h0_kernel<<<(int)((total + 255) / 256), 256>>>(h0, h0bf);
    }

    // 7. aggregation: agg = scatter_mean(edge_weight * h0bf[src], dst)
    aggregate_kernel<<<NN, 160>>>(h0bf, rowptr, cnt, edges, agg);

    // 8. GEMM2: h = relu(h0 + agg @ W + b)
    {
        dim3 grid(NPAD / 128, (NN + 127) / 128);
        gemm_hmma<false, true><<<grid, 256, GEMM_SMEM>>>(
            agg, nullptr, (__nv_bfloat16*)p_wh, (__nv_bfloat16*)p_wl,
            b, h0, h, NN, HID, HID, 0, K2PAD);
    }
}

// round 16
// speedup vs baseline: 1.0374x; 1.0374x over previous
#include <cuda_runtime.h>
#include <cuda_bf16.h>
#include <cstdint>

#define NN    50000
#define EE    800000
#define NODE_D 128
#define EDGE_D 16
#define HID   300

#define NPAD  384
#define K1PAD 192           // GEMM1 K=144
#define K2PAD 320           // GEMM2 K=300

typedef unsigned long long u64;

// ---------------- scratch (device globals; no allocs allowed) ----------------
__device__ float g_inc[NN * EDGE_D + 64];
__device__ float g_agg[(size_t)NN * HID + 64];
__device__ float g_h0[(size_t)NN * HID + 64];
__device__ int   g_cnt[NN];
__device__ int   g_rowptr[NN];
__device__ int   g_cursor[NN];
__device__ int4  g_edges[EE];              // packed (src, eid, w_bits, 0)
__device__ __nv_bfloat16 g_w0t_hi[NPAD * K1PAD];
__device__ __nv_bfloat16 g_w0t_lo[NPAD * K1PAD];
__device__ __nv_bfloat16 g_wt_hi[NPAD * K2PAD];
__device__ __nv_bfloat16 g_wt_lo[NPAD * K2PAD];

// ---------------- asm helpers ----------------
__device__ __forceinline__ uint32_t smem_u32(const void* p) {
    return (uint32_t)__cvta_generic_to_shared(p);
}
__device__ __forceinline__ void ldsm_x4(uint32_t* r, uint32_t addr) {
    asm volatile("ldmatrix.sync.aligned.m8n8.x4.shared.b16 {%0,%1,%2,%3}, [%4];"
                 : "=r"(r[0]), "=r"(r[1]), "=r"(r[2]), "=r"(r[3]) : "r"(addr));
}
__device__ __forceinline__ void mma_bf16(float* d, const uint32_t* a, const uint32_t* b) {
    asm volatile(
        "mma.sync.aligned.m16n8k16.row.col.f32.bf16.bf16.f32 "
        "{%0,%1,%2,%3}, {%4,%5,%6,%7}, {%8,%9}, {%0,%1,%2,%3};"
        : "+f"(d[0]), "+f"(d[1]), "+f"(d[2]), "+f"(d[3])
        : "r"(a[0]), "r"(a[1]), "r"(a[2]), "r"(a[3]), "r"(b[0]), "r"(b[1]));
}
__device__ __forceinline__ void cp_async16(uint32_t dst, const void* src) {
    asm volatile("cp.async.cg.shared.global [%0], [%1], 16;" :: "r"(dst), "l"(src));
}
__device__ __forceinline__ void cp_commit() {
    asm volatile("cp.async.commit_group;" ::: "memory");
}
__device__ __forceinline__ void cp_wait0() {
    asm volatile("cp.async.wait_group 0;" ::: "memory");
}

// ------- kernel 1 (fused): zero cnt + prep both weights (independent) --------
// idx layout: [0, NN)                         -> cnt zero
//             [NN, NN + NPAD*K1PAD)           -> W0 transpose/split
//             [NN + NPAD*K1PAD, ... + K2PAD)  -> W  transpose/split
#define PREP_TOTAL (NN + NPAD * K1PAD + NPAD * K2PAD)
__global__ void fused_prep_kernel(const float* __restrict__ W0,
                                  const float* __restrict__ W,
                                  int* __restrict__ cnt,
                                  __nv_bfloat16* __restrict__ w0hi,
                                  __nv_bfloat16* __restrict__ w0lo,
                                  __nv_bfloat16* __restrict__ whi,
                                  __nv_bfloat16* __restrict__ wlo) {
    int idx = blockIdx.x * blockDim.x + threadIdx.x;
    if (idx < NN) {
        cnt[idx] = 0;
        return;
    }
    idx -= NN;
    if (idx < NPAD * K1PAD) {
        int n = idx / K1PAD;
        int k = idx - n * K1PAD;
        float v = (k < NODE_D + EDGE_D && n < HID)
                      ? W0[(size_t)k * HID + n] : 0.f;
        __nv_bfloat16 h = __float2bfloat16(v);
        w0hi[idx] = h;
        w0lo[idx] = __float2bfloat16(v - __bfloat162float(h));
        return;
    }
    idx -= NPAD * K1PAD;
    if (idx < NPAD * K2PAD) {
        int n = idx / K2PAD;
        int k = idx - n * K2PAD;
        float v = (k < HID && n < HID) ? W[(size_t)k * HID + n] : 0.f;
        __nv_bfloat16 h = __float2bfloat16(v);
        whi[idx] = h;
        wlo[idx] = __float2bfloat16(v - __bfloat162float(h));
    }
}

// ---------------- kernel 2: dst histogram ----------------
__global__ void hist_kernel(const int* __restrict__ edge_index, int* __restrict__ cnt) {
    int e = blockIdx.x * blockDim.x + threadIdx.x;
    if (e < EE) atomicAdd(&cnt[edge_index[EE + e]], 1);
}

// ---------------- kernel 3: single-block exclusive scan ----------------
__global__ void scan_kernel(const int* __restrict__ cnt,
                            int* __restrict__ rowptr,
                            int* __restrict__ cursor) {
    __shared__ int part[1024];
    const int n = NN;
    int t = threadIdx.x;
    const int chunk = (n + 1023) / 1024;
    int beg = t * chunk;
    int end = beg + chunk;
    if (beg > n) beg = n;
    if (end > n) end = n;
    int s = 0;
    for (int i = beg; i < end; i++) s += cnt[i];
    part[t] = s;
    __syncthreads();
    for (int off = 1; off < 1024; off <<= 1) {
        int v = (t >= off) ? part[t - off] : 0;
        __syncthreads();
        part[t] += v;
        __syncthreads();
    }
    int run = part[t] - s;
    for (int i = beg; i < end; i++) {
        rowptr[i] = run;
        cursor[i] = run;
        run += cnt[i];
    }
}

// ---------------- kernel 4: bucket edges by dst (packed int4) ----------------
__global__ void fill_kernel(const float* __restrict__ edge_weight,
                            const int* __restrict__ edge_index,
                            int* __restrict__ cursor,
                            int4* __restrict__ edges) {
    int e = blockIdx.x * blockDim.x + threadIdx.x;
    if (e >= EE) return;
    int src = edge_index[e];
    int dst = edge_index[EE + e];
    int pos = atomicAdd(&cursor[dst], 1);
    edges[pos] = make_int4(src, e, __float_as_int(edge_weight[e]), 0);
}

// ---------------- kernel 5: inc via CSR gather (no atomics) ------------------
__global__ __launch_bounds__(256)
void inc_csr_kernel(const float* __restrict__ edge_attr,
                    const int* __restrict__ rowptr,
                    const int* __restrict__ cnt_arr,
                    const int4* __restrict__ edges,
                    float* __restrict__ inc) {
    int node = blockIdx.x * 8 + (threadIdx.x >> 5);
    if (node >= NN) return;
    int lane = threadIdx.x & 31;
    int start = rowptr[node];
    int cnt = cnt_arr[node];
    int d = lane & 15;
    int half = lane >> 4;
    float acc = 0.f;
    for (int j = half; j < cnt; j += 2) {
        int4 ed = edges[start + j];
        float w = __int_as_float(ed.z);
        acc += w * edge_attr[ed.y * EDGE_D + d];
    }
    acc += __shfl_xor_sync(0xffffffffu, acc, 16);
    if (half == 0) inc[node * EDGE_D + d] = acc;
}

// ---------------- split-bf16 HMMA GEMM, half-chunk pipelined -----------------
#define HSTR 40                          // 32 k + 8 pad (80B row stride)
#define TILEH (128 * HSTR)
#define BUFSET (4 * TILEH)
#define GEMM_SMEM (2 * BUFSET * 2)       // 81920 B

template<int JPMAX>
__device__ __forceinline__ void mma_phase(
    float (&acc)[2][8][4],
    const __nv_bfloat16* Ah, const __nv_bfloat16* Al,
    const __nv_bfloat16* Bh, const __nv_bfloat16* Bl,
    int ksteps, int warp_m, int warp_n,
    int a_row_l, int a_kh, int b_mat, int b_rr)
{
    for (int ks = 0; ks < ksteps; ks++) {
        int k0 = ks * 16;
        uint32_t ah[2][4], al[2][4];
#pragma unroll
        for (int i = 0; i < 2; i++) {
            int arow = warp_m * 32 + i * 16 + a_row_l;
            ldsm_x4(ah[i], smem_u32(Ah + arow * HSTR + k0 + a_kh));
            ldsm_x4(al[i], smem_u32(Al + arow * HSTR + k0 + a_kh));
        }
#pragma unroll
        for (int jp = 0; jp < JPMAX; jp++) {
            int brow = warp_n * 64 + (jp * 2 + (b_mat >> 1)) * 8 + b_rr;
            int bk   = k0 + (b_mat & 1) * 8;
            uint32_t bh[4], bl[4];
            ldsm_x4(bh, smem_u32(Bh + brow * HSTR + bk));
            ldsm_x4(bl, smem_u32(Bl + brow * HSTR + bk));
#pragma unroll
            for (int i = 0; i < 2; i++) {
                mma_bf16(acc[i][2*jp],   ah[i], &bh[0]);
                mma_bf16(acc[i][2*jp],   al[i], &bh[0]);
                mma_bf16(acc[i][2*jp],   ah[i], &bl[0]);
                mma_bf16(acc[i][2*jp+1], ah[i], &bh[2]);
                mma_bf16(acc[i][2*jp+1], al[i], &bh[2]);
                mma_bf16(acc[i][2*jp+1], ah[i], &bl[2]);
            }
        }
    }
}

template<bool CONCAT>
__device__ __forceinline__ void load_A_regs(
    float (&va)[2][8], const float* __restrict__ A, const float* __restrict__ A2,
    int m0, int khbase, int M, int K, int K1, int tid)
{
#pragma unroll
    for (int it = 0; it < 2; it++) {
        int idx = tid + it * 256;
        int row = idx >> 2, grp = idx & 3;
        int gm = m0 + row;
        int gk = khbase + grp * 8;
        if (gm < M && gk + 8 <= K) {
            const float* p;
            if (CONCAT) p = (gk < K1) ? (A + (size_t)gm * K1 + gk)
                                      : (A2 + (size_t)gm * (K - K1) + (gk - K1));
            else        p = A + (size_t)gm * K + gk;
            float4 u0 = *reinterpret_cast<const float4*>(p);
            float4 u1 = *reinterpret_cast<const float4*>(p + 4);
            va[it][0]=u0.x; va[it][1]=u0.y; va[it][2]=u0.z; va[it][3]=u0.w;
            va[it][4]=u1.x; va[it][5]=u1.y; va[it][6]=u1.z; va[it][7]=u1.w;
        } else {
#pragma unroll
            for (int i = 0; i < 8; i++) {
                int kk = gk + i;
                float val = 0.f;
                if (gm < M && kk < K) {
                    if (CONCAT) val = (kk < K1) ? A[(size_t)gm * K1 + kk]
                                                : A2[(size_t)gm * (K - K1) + (kk - K1)];
                    else        val = A[(size_t)gm * K + kk];
                }
                va[it][i] = val;
            }
        }
    }
}

__device__ __forceinline__ void store_A_split(
    const float (&va)[2][8], __nv_bfloat16* Ah, __nv_bfloat16* Al, int tid)
{
#pragma unroll
    for (int it = 0; it < 2; it++) {
        int idx = tid + it * 256;
        int row = idx >> 2, grp = idx & 3;
        uint32_t hw[4], lw[4];
#pragma unroll
        for (int i = 0; i < 4; i++) {
            float v0 = va[it][2*i], v1 = va[it][2*i+1];
            __nv_bfloat16 h0b = __float2bfloat16(v0);
            __nv_bfloat16 h1b = __float2bfloat16(v1);
            __nv_bfloat16 l0b = __float2bfloat16(v0 - __bfloat162float(h0b));
            __nv_bfloat16 l1b = __float2bfloat16(v1 - __bfloat162float(h1b));
            hw[i] = (uint32_t)__bfloat16_as_ushort(h0b) | ((uint32_t)__bfloat16_as_ushort(h1b) << 16);
            lw[i] = (uint32_t)__bfloat16_as_ushort(l0b) | ((uint32_t)__bfloat16_as_ushort(l1b) << 16);
        }
        int off = row * HSTR + grp * 8;
        *reinterpret_cast<uint4*>(Ah + off) = make_uint4(hw[0], hw[1], hw[2], hw[3]);
        *reinterpret_cast<uint4*>(Al + off) = make_uint4(lw[0], lw[1], lw[2], lw[3]);
    }
}

__device__ __forceinline__ void fill_B_async(
    const __nv_bfloat16* __restrict__ Bhi, const __nv_bfloat16* __restrict__ Blo,
    __nv_bfloat16* Bh, __nv_bfloat16* Bl, int n0, int khbase, int KPAD, int tid)
{
#pragma unroll
    for (int it = 0; it < 2; it++) {
        int idx = tid + it * 256;
        int row = idx >> 2, grp = idx & 3;
        size_t gidx = (size_t)(n0 + row) * KPAD + khbase + grp * 8;
        int off = row * HSTR + grp * 8;
        cp_async16(smem_u32(Bh + off), Bhi + gidx);
        cp_async16(smem_u32(Bl + off), Blo + gidx);
    }
}

template<bool CONCAT, bool RESID>
__global__ __launch_bounds__(256, 2)
void gemm_hmma(const float* __restrict__ A, const float* __restrict__ A2,
               const __nv_bfloat16* __restrict__ Bhi, const __nv_bfloat16* __restrict__ Blo,
               const float* __restrict__ bias, const float* __restrict__ resid,
               float* __restrict__ C, int M, int Nn, int K, int K1, int KPAD) {
    extern __shared__ __nv_bfloat16 sm[];

    int tid = threadIdx.x;
    int wid = tid >> 5, lid = tid & 31;
    int warp_m = wid >> 1;          // 0..3
    int warp_n = wid & 1;           // 0..1
    int m0 = blockIdx.y * 128;
    int n0 = blockIdx.x * 128;

    int jp_max = 4;
    {
        int cols_needed = Nn - (n0 + warp_n * 64);
        if (cols_needed <= 0) jp_max = 0;
        else if (cols_needed < 64) jp_max = (cols_needed + 15) >> 4;
    }

    float acc[2][8][4];
#pragma unroll
    for (int i = 0; i < 2; i++)
#pragma unroll
        for (int j = 0; j < 8; j++)
#pragma unroll
            for (int q = 0; q < 4; q++) acc[i][j][q] = 0.f;

    int a_row_l = lid & 15;
    int a_kh    = (lid >> 4) * 8;
    int b_mat   = lid >> 3;
    int b_rr    = lid & 7;

    const int nhalf = (K + 31) >> 5;
    float va[2][8];

    // ---- prologue: fill half 0 ----
    fill_B_async(Bhi, Blo, sm + 2 * TILEH, sm + 3 * TILEH, n0, 0, KPAD, tid);
    cp_commit();
    load_A_regs<CONCAT>(va, A, A2, m0, 0, M, K, K1, tid);
    store_A_split(va, sm, sm + TILEH, tid);
    cp_wait0();
    __syncthreads();

    for (int h = 0; h < nhalf; h++) {
        __nv_bfloat16* cur = sm + (h & 1) * BUFSET;
        __nv_bfloat16* nxt = sm + ((h + 1) & 1) * BUFSET;
        bool pf = (h + 1 < nhalf);
        if (pf) {
            fill_B_async(Bhi, Blo, nxt + 2 * TILEH, nxt + 3 * TILEH,
                         n0, (h + 1) << 5, KPAD, tid);
            cp_commit();
            load_A_regs<CONCAT>(va, A, A2, m0, (h + 1) << 5, M, K, K1, tid);
        }

        int rem = K - (h << 5);
        int ksteps = (rem + 15) >> 4;
        if (ksteps > 2) ksteps = 2;
        if (jp_max == 4)
            mma_phase<4>(acc, cur, cur + TILEH, cur + 2 * TILEH, cur + 3 * TILEH,
                         ksteps, warp_m, warp_n, a_row_l, a_kh, b_mat, b_rr);
        else if (jp_max == 3)
            mma_phase<3>(acc, cur, cur + TILEH, cur + 2 * TILEH, cur + 3 * TILEH,
                         ksteps, warp_m, warp_n, a_row_l, a_kh, b_mat, b_rr);

        if (pf) {
            store_A_split(va, nxt, nxt + TILEH, tid);
            cp_wait0();
        }
        __syncthreads();
    }

    // ---- epilogue: bias (+resid) + relu ----
    int tq = lid >> 2;
    int tr = lid & 3;
    int row_base = m0 + warp_m * 32 + tq;
    int col_base = n0 + warp_n * 64 + tr * 2;
#pragma unroll
    for (int i = 0; i < 2; i++) {
#pragma unroll
        for (int j = 0; j < 8; j++) {
            int col = col_base + j * 8;
            if (col >= Nn) continue;
            float2 bs = *reinterpret_cast<const float2*>(bias + col);
#pragma unroll
            for (int half = 0; half < 2; half++) {
                int row = row_base + i * 16 + half * 8;
                if (row >= M) continue;
                float v0 = acc[i][j][2*half + 0] + bs.x;
                float v1 = acc[i][j][2*half + 1] + bs.y;
                if (RESID) {
                    float2 rr = *reinterpret_cast<const float2*>(resid + (size_t)row * Nn + col);
                    v0 += rr.x; v1 += rr.y;
                }
                float2 o;
                o.x = fmaxf(v0, 0.f);
                o.y = fmaxf(v1, 0.f);
                *reinterpret_cast<float2*>(C + (size_t)row * Nn + col) = o;
            }
        }
    }
}

// ---------------- per-node CSR aggregation (scatter-mean, fp32) --------------
__global__ __launch_bounds__(128)
void aggregate_kernel(const float* __restrict__ h0,
                      const int* __restrict__ rowptr,
                      const int* __restrict__ cnt_arr,
                      const int4* __restrict__ edges,
                      float* __restrict__ agg) {
    int i = blockIdx.x;
    int t = threadIdx.x;
    int start = rowptr[i];
    int cnt = cnt_arr[i];
    __shared__ int s_src[128];
    __shared__ float s_w[128];
    float acc0 = 0.f, acc1 = 0.f, acc2 = 0.f;
    for (int base = 0; base < cnt; base += 128) {
        int m = cnt - base; if (m > 128) m = 128;
        if (t < m) {
            int4 ed = edges[start + base + t];
            s_src[t] = ed.x;
            s_w[t]   = __int_as_float(ed.z);
        }
        __syncthreads();
        for (int j = 0; j < m; j++) {
            const float* row = h0 + (size_t)s_src[j] * HID;
            float w = s_w[j];
            acc0 += w * row[t];
            acc1 += w * row[t + 128];
            if (t + 256 < HID) acc2 += w * row[t + 256];
        }
        __syncthreads();
    }
    float inv = 1.0f / fmaxf((float)cnt, 1.0f);
    float* out = agg + (size_t)i * HID;
    out[t] = acc0 * inv;
    out[t + 128] = acc1 * inv;
    if (t + 256 < HID) out[t + 256] = acc2 * inv;
}

// ---------------- launch ----------------
extern "C" void kernel_launch(void* const* d_in, const int* in_sizes, int n_in,
                              void* d_out, int out_size) {
    const float* x = nullptr;
    const float* edge_attr = nullptr;
    const float* edge_weight = nullptr;
    const float* W0 = nullptr;
    const float* b0 = nullptr;
    const float* W  = nullptr;
    const float* b  = nullptr;
    const int*   edge_index = nullptr;

    for (int i = 0; i < n_in; i++) {
        int s = in_sizes[i];
        switch (s) {
            case NN * NODE_D:      x = (const float*)d_in[i]; break;
            case EE * EDGE_D:      edge_attr = (const float*)d_in[i]; break;
            case EE:               edge_weight = (const float*)d_in[i]; break;
            case (NODE_D + EDGE_D) * HID: W0 = (const float*)d_in[i]; break;
            case HID * HID:        W = (const float*)d_in[i]; break;
            case 2 * EE:           edge_index = (const int*)d_in[i]; break;
            case HID:
                if (!b0) b0 = (const float*)d_in[i];
                else     b  = (const float*)d_in[i];
                break;
            default: break; // node_weight unused
        }
    }
    if (!b) b = b0;

    void *p_inc, *p_agg, *p_h0, *p_cnt, *p_rowptr, *p_cursor, *p_edges;
    void *p_w0h, *p_w0l, *p_wh, *p_wl;
    cudaGetSymbolAddress(&p_inc,    g_inc);
    cudaGetSymbolAddress(&p_agg,    g_agg);
    cudaGetSymbolAddress(&p_h0,     g_h0);
    cudaGetSymbolAddress(&p_cnt,    g_cnt);
    cudaGetSymbolAddress(&p_rowptr, g_rowptr);
    cudaGetSymbolAddress(&p_cursor, g_cursor);
    cudaGetSymbolAddress(&p_edges,  g_edges);
    cudaGetSymbolAddress(&p_w0h,    g_w0t_hi);
    cudaGetSymbolAddress(&p_w0l,    g_w0t_lo);
    cudaGetSymbolAddress(&p_wh,     g_wt_hi);
    cudaGetSymbolAddress(&p_wl,     g_wt_lo);

    float* inc     = (float*)p_inc;
    float* agg     = (float*)p_agg;
    int*   cnt     = (int*)p_cnt;
    int*   rowptr  = (int*)p_rowptr;
    int*   cursor  = (int*)p_cursor;
    int4*  edges   = (int4*)p_edges;

    float* h = (float*)d_out;
    float* h0 = (out_size >= 2 * NN * HID) ? (float*)d_out + (size_t)NN * HID
                                           : (float*)p_h0;

    cudaFuncSetAttribute(gemm_hmma<true,  false>,
                         cudaFuncAttributeMaxDynamicSharedMemorySize, GEMM_SMEM);
    cudaFuncSetAttribute(gemm_hmma<false, true>,
                         cudaFuncAttributeMaxDynamicSharedMemorySize, GEMM_SMEM);

    // 1. fused: zero cnt + weight prep (launch #1)
    fused_prep_kernel<<<(PREP_TOTAL + 255) / 256, 256>>>(
        W0, W, cnt,
        (__nv_bfloat16*)p_w0h, (__nv_bfloat16*)p_w0l,
        (__nv_bfloat16*)p_wh,  (__nv_bfloat16*)p_wl);

    // 2. dst histogram (launch #2)
    hist_kernel<<<(EE + 255) / 256, 256>>>(edge_index, cnt);

    // 3. scan -> rowptr/cursor (launch #3)
    scan_kernel<<<1, 1024>>>(cnt, rowptr, cursor);

    // 4. bucket edges (launch #4)
    fill_kernel<<<(EE + 255) / 256, 256>>>(edge_weight, edge_index, cursor, edges);

    // 5. inc via CSR gather (launch #5)
    inc_csr_kernel<<<(NN + 7) / 8, 256>>>(edge_attr, rowptr, cnt, edges, inc);

    // 6. GEMM1 (launch #6 -> captured by ncu -s 5 -c 1)
    {
        dim3 grid(NPAD / 128, (NN + 127) / 128);
        gemm_hmma<true, false><<<grid, 256, GEMM_SMEM>>>(
            x, inc, (__nv_bfloat16*)p_w0h, (__nv_bfloat16*)p_w0l,
            b0, nullptr, h0, NN, HID, NODE_D + EDGE_D, NODE_D, K1PAD);
    }

    // 7. aggregation: agg = scatter_mean(edge_weight * h0[src], dst)
    aggregate_kernel<<<NN, 128>>>(h0, rowptr, cnt, edges, agg);

    // 8. GEMM2: h = relu(h0 + agg @ W + b)
    {
        dim3 grid(NPAD / 128, (NN + 127) / 128);
        gemm_hmma<false, true><<<grid, 256, GEMM_SMEM>>>(
            agg, nullptr, (__nv_bfloat16*)p_wh, (__nv_bfloat16*)p_wl,
            b, h0, h, NN, HID, HID, 0, K2PAD);
    }
}

// round 17
// speedup vs baseline: 1.0449x; 1.0073x over previous
#include <cuda_runtime.h>
#include <cuda_bf16.h>
#include <cstdint>

#define NN    50000
#define EE    800000
#define NODE_D 128
#define EDGE_D 16
#define HID   300

#define NPAD  384
#define K1PAD 192           // GEMM1 K=144
#define K2PAD 320           // GEMM2 K=300

typedef unsigned long long u64;

// ---------------- scratch (device globals; no allocs allowed) ----------------
__device__ float g_inc[NN * EDGE_D + 64];
__device__ float g_agg[(size_t)NN * HID + 64];
__device__ float g_h0[(size_t)NN * HID + 64];
__device__ int   g_cnt[NN];
__device__ int   g_rowptr[NN];
__device__ int   g_cursor[NN];
__device__ int4  g_edges[EE];              // packed (src, eid, w_bits, 0)
__device__ __nv_bfloat16 g_w0t_hi[NPAD * K1PAD];
__device__ __nv_bfloat16 g_w0t_lo[NPAD * K1PAD];
__device__ __nv_bfloat16 g_wt_hi[NPAD * K2PAD];
__device__ __nv_bfloat16 g_wt_lo[NPAD * K2PAD];

// ---------------- asm helpers ----------------
__device__ __forceinline__ uint32_t smem_u32(const void* p) {
    return (uint32_t)__cvta_generic_to_shared(p);
}
__device__ __forceinline__ void ldsm_x4(uint32_t* r, uint32_t addr) {
    asm volatile("ldmatrix.sync.aligned.m8n8.x4.shared.b16 {%0,%1,%2,%3}, [%4];"
                 : "=r"(r[0]), "=r"(r[1]), "=r"(r[2]), "=r"(r[3]) : "r"(addr));
}
__device__ __forceinline__ void mma_bf16(float* d, const uint32_t* a, const uint32_t* b) {
    asm volatile(
        "mma.sync.aligned.m16n8k16.row.col.f32.bf16.bf16.f32 "
        "{%0,%1,%2,%3}, {%4,%5,%6,%7}, {%8,%9}, {%0,%1,%2,%3};"
        : "+f"(d[0]), "+f"(d[1]), "+f"(d[2]), "+f"(d[3])
        : "r"(a[0]), "r"(a[1]), "r"(a[2]), "r"(a[3]), "r"(b[0]), "r"(b[1]));
}
__device__ __forceinline__ void cp_async16(uint32_t dst, const void* src) {
    asm volatile("cp.async.cg.shared.global [%0], [%1], 16;" :: "r"(dst), "l"(src));
}
__device__ __forceinline__ void cp_commit() {
    asm volatile("cp.async.commit_group;" ::: "memory");
}
__device__ __forceinline__ void cp_wait0() {
    asm volatile("cp.async.wait_group 0;" ::: "memory");
}

// ------- kernel 1 (fused): zero cnt + prep both weights (independent) --------
#define PREP_TOTAL (NN + NPAD * K1PAD + NPAD * K2PAD)
__global__ void fused_prep_kernel(const float* __restrict__ W0,
                                  const float* __restrict__ W,
                                  int* __restrict__ cnt,
                                  __nv_bfloat16* __restrict__ w0hi,
                                  __nv_bfloat16* __restrict__ w0lo,
                                  __nv_bfloat16* __restrict__ whi,
                                  __nv_bfloat16* __restrict__ wlo) {
    int idx = blockIdx.x * blockDim.x + threadIdx.x;
    if (idx < NN) {
        cnt[idx] = 0;
        return;
    }
    idx -= NN;
    if (idx < NPAD * K1PAD) {
        int n = idx / K1PAD;
        int k = idx - n * K1PAD;
        float v = (k < NODE_D + EDGE_D && n < HID)
                      ? W0[(size_t)k * HID + n] : 0.f;
        __nv_bfloat16 h = __float2bfloat16(v);
        w0hi[idx] = h;
        w0lo[idx] = __float2bfloat16(v - __bfloat162float(h));
        return;
    }
    idx -= NPAD * K1PAD;
    if (idx < NPAD * K2PAD) {
        int n = idx / K2PAD;
        int k = idx - n * K2PAD;
        float v = (k < HID && n < HID) ? W[(size_t)k * HID + n] : 0.f;
        __nv_bfloat16 h = __float2bfloat16(v);
        whi[idx] = h;
        wlo[idx] = __float2bfloat16(v - __bfloat162float(h));
    }
}

// ---------------- kernel 2: dst histogram ----------------
__global__ void hist_kernel(const int* __restrict__ edge_index, int* __restrict__ cnt) {
    int e = blockIdx.x * blockDim.x + threadIdx.x;
    if (e < EE) atomicAdd(&cnt[edge_index[EE + e]], 1);
}

// ---------------- kernel 3: single-block exclusive scan ----------------
__global__ void scan_kernel(const int* __restrict__ cnt,
                            int* __restrict__ rowptr,
                            int* __restrict__ cursor) {
    __shared__ int part[1024];
    const int n = NN;
    int t = threadIdx.x;
    const int chunk = (n + 1023) / 1024;
    int beg = t * chunk;
    int end = beg + chunk;
    if (beg > n) beg = n;
    if (end > n) end = n;
    int s = 0;
    for (int i = beg; i < end; i++) s += cnt[i];
    part[t] = s;
    __syncthreads();
    for (int off = 1; off < 1024; off <<= 1) {
        int v = (t >= off) ? part[t - off] : 0;
        __syncthreads();
        part[t] += v;
        __syncthreads();
    }
    int run = part[t] - s;
    for (int i = beg; i < end; i++) {
        rowptr[i] = run;
        cursor[i] = run;
        run += cnt[i];
    }
}

// ---------------- kernel 4: bucket edges by dst (packed int4) ----------------
__global__ void fill_kernel(const float* __restrict__ edge_weight,
                            const int* __restrict__ edge_index,
                            int* __restrict__ cursor,
                            int4* __restrict__ edges) {
    int e = blockIdx.x * blockDim.x + threadIdx.x;
    if (e >= EE) return;
    int src = edge_index[e];
    int dst = edge_index[EE + e];
    int pos = atomicAdd(&cursor[dst], 1);
    edges[pos] = make_int4(src, e, __float_as_int(edge_weight[e]), 0);
}

// ---------------- kernel 5: inc via CSR gather (no atomics) ------------------
__global__ __launch_bounds__(256)
void inc_csr_kernel(const float* __restrict__ edge_attr,
                    const int* __restrict__ rowptr,
                    const int* __restrict__ cnt_arr,
                    const int4* __restrict__ edges,
                    float* __restrict__ inc) {
    int node = blockIdx.x * 8 + (threadIdx.x >> 5);
    if (node >= NN) return;
    int lane = threadIdx.x & 31;
    int start = rowptr[node];
    int cnt = cnt_arr[node];
    int d = lane & 15;
    int half = lane >> 4;
    float acc = 0.f;
    for (int j = half; j < cnt; j += 2) {
        int4 ed = edges[start + j];
        float w = __int_as_float(ed.z);
        acc += w * edge_attr[ed.y * EDGE_D + d];
    }
    acc += __shfl_xor_sync(0xffffffffu, acc, 16);
    if (half == 0) inc[node * EDGE_D + d] = acc;
}

// ---------------- split-bf16 HMMA GEMM, half-chunk pipelined -----------------
#define HSTR 40                          // 32 k + 8 pad (80B row stride)
#define TILEH (128 * HSTR)
#define BUFSET (4 * TILEH)
#define GEMM_SMEM (2 * BUFSET * 2)       // 81920 B

template<int JPMAX>
__device__ __forceinline__ void mma_phase(
    float (&acc)[2][8][4],
    const __nv_bfloat16* Ah, const __nv_bfloat16* Al,
    const __nv_bfloat16* Bh, const __nv_bfloat16* Bl,
    int ksteps, int warp_m, int warp_n,
    int a_row_l, int a_kh, int b_mat, int b_rr)
{
    for (int ks = 0; ks < ksteps; ks++) {
        int k0 = ks * 16;
        uint32_t ah[2][4], al[2][4];
#pragma unroll
        for (int i = 0; i < 2; i++) {
            int arow = warp_m * 32 + i * 16 + a_row_l;
            ldsm_x4(ah[i], smem_u32(Ah + arow * HSTR + k0 + a_kh));
            ldsm_x4(al[i], smem_u32(Al + arow * HSTR + k0 + a_kh));
        }
#pragma unroll
        for (int jp = 0; jp < JPMAX; jp++) {
            int brow = warp_n * 64 + (jp * 2 + (b_mat >> 1)) * 8 + b_rr;
            int bk   = k0 + (b_mat & 1) * 8;
            uint32_t bh[4], bl[4];
            ldsm_x4(bh, smem_u32(Bh + brow * HSTR + bk));
            ldsm_x4(bl, smem_u32(Bl + brow * HSTR + bk));
#pragma unroll
            for (int i = 0; i < 2; i++) {
                mma_bf16(acc[i][2*jp],   ah[i], &bh[0]);
                mma_bf16(acc[i][2*jp],   al[i], &bh[0]);
                mma_bf16(acc[i][2*jp],   ah[i], &bl[0]);
                mma_bf16(acc[i][2*jp+1], ah[i], &bh[2]);
                mma_bf16(acc[i][2*jp+1], al[i], &bh[2]);
                mma_bf16(acc[i][2*jp+1], ah[i], &bl[2]);
            }
        }
    }
}

template<bool CONCAT>
__device__ __forceinline__ void load_A_regs(
    float (&va)[2][8], const float* __restrict__ A, const float* __restrict__ A2,
    int m0, int khbase, int M, int K, int K1, int tid)
{
#pragma unroll
    for (int it = 0; it < 2; it++) {
        int idx = tid + it * 256;
        int row = idx >> 2, grp = idx & 3;
        int gm = m0 + row;
        int gk = khbase + grp * 8;
        if (gm < M && gk + 8 <= K) {
            const float* p;
            if (CONCAT) p = (gk < K1) ? (A + (size_t)gm * K1 + gk)
                                      : (A2 + (size_t)gm * (K - K1) + (gk - K1));
            else        p = A + (size_t)gm * K + gk;
            float4 u0 = *reinterpret_cast<const float4*>(p);
            float4 u1 = *reinterpret_cast<const float4*>(p + 4);
            va[it][0]=u0.x; va[it][1]=u0.y; va[it][2]=u0.z; va[it][3]=u0.w;
            va[it][4]=u1.x; va[it][5]=u1.y; va[it][6]=u1.z; va[it][7]=u1.w;
        } else {
#pragma unroll
            for (int i = 0; i < 8; i++) {
                int kk = gk + i;
                float val = 0.f;
                if (gm < M && kk < K) {
                    if (CONCAT) val = (kk < K1) ? A[(size_t)gm * K1 + kk]
                                                : A2[(size_t)gm * (K - K1) + (kk - K1)];
                    else        val = A[(size_t)gm * K + kk];
                }
                va[it][i] = val;
            }
        }
    }
}

__device__ __forceinline__ void store_A_split(
    const float (&va)[2][8], __nv_bfloat16* Ah, __nv_bfloat16* Al, int tid)
{
#pragma unroll
    for (int it = 0; it < 2; it++) {
        int idx = tid + it * 256;
        int row = idx >> 2, grp = idx & 3;
        uint32_t hw[4], lw[4];
#pragma unroll
        for (int i = 0; i < 4; i++) {
            float v0 = va[it][2*i], v1 = va[it][2*i+1];
            __nv_bfloat16 h0b = __float2bfloat16(v0);
            __nv_bfloat16 h1b = __float2bfloat16(v1);
            __nv_bfloat16 l0b = __float2bfloat16(v0 - __bfloat162float(h0b));
            __nv_bfloat16 l1b = __float2bfloat16(v1 - __bfloat162float(h1b));
            hw[i] = (uint32_t)__bfloat16_as_ushort(h0b) | ((uint32_t)__bfloat16_as_ushort(h1b) << 16);
            lw[i] = (uint32_t)__bfloat16_as_ushort(l0b) | ((uint32_t)__bfloat16_as_ushort(l1b) << 16);
        }
        int off = row * HSTR + grp * 8;
        *reinterpret_cast<uint4*>(Ah + off) = make_uint4(hw[0], hw[1], hw[2], hw[3]);
        *reinterpret_cast<uint4*>(Al + off) = make_uint4(lw[0], lw[1], lw[2], lw[3]);
    }
}

__device__ __forceinline__ void fill_B_async(
    const __nv_bfloat16* __restrict__ Bhi, const __nv_bfloat16* __restrict__ Blo,
    __nv_bfloat16* Bh, __nv_bfloat16* Bl, int n0, int khbase, int KPAD, int tid)
{
#pragma unroll
    for (int it = 0; it < 2; it++) {
        int idx = tid + it * 256;
        int row = idx >> 2, grp = idx & 3;
        size_t gidx = (size_t)(n0 + row) * KPAD + khbase + grp * 8;
        int off = row * HSTR + grp * 8;
        cp_async16(smem_u32(Bh + off), Bhi + gidx);
        cp_async16(smem_u32(Bl + off), Blo + gidx);
    }
}

template<bool CONCAT, bool RESID>
__global__ __launch_bounds__(256, 2)
void gemm_hmma(const float* __restrict__ A, const float* __restrict__ A2,
               const __nv_bfloat16* __restrict__ Bhi, const __nv_bfloat16* __restrict__ Blo,
               const float* __restrict__ bias, const float* __restrict__ resid,
               float* __restrict__ C, int M, int Nn, int K, int K1, int KPAD) {
    extern __shared__ __nv_bfloat16 sm[];

    int tid = threadIdx.x;
    int wid = tid >> 5, lid = tid & 31;
    int warp_m = wid >> 1;          // 0..3
    int warp_n = wid & 1;           // 0..1
    int m0 = blockIdx.y * 128;
    int n0 = blockIdx.x * 128;

    int jp_max = 4;
    {
        int cols_needed = Nn - (n0 + warp_n * 64);
        if (cols_needed <= 0) jp_max = 0;
        else if (cols_needed < 64) jp_max = (cols_needed + 15) >> 4;
    }

    float acc[2][8][4];
#pragma unroll
    for (int i = 0; i < 2; i++)
#pragma unroll
        for (int j = 0; j < 8; j++)
#pragma unroll
            for (int q = 0; q < 4; q++) acc[i][j][q] = 0.f;

    int a_row_l = lid & 15;
    int a_kh    = (lid >> 4) * 8;
    int b_mat   = lid >> 3;
    int b_rr    = lid & 7;

    const int nhalf = (K + 31) >> 5;
    float va[2][8];

    // ---- prologue: fill half 0 ----
    fill_B_async(Bhi, Blo, sm + 2 * TILEH, sm + 3 * TILEH, n0, 0, KPAD, tid);
    cp_commit();
    load_A_regs<CONCAT>(va, A, A2, m0, 0, M, K, K1, tid);
    store_A_split(va, sm, sm + TILEH, tid);
    cp_wait0();
    __syncthreads();

    for (int h = 0; h < nhalf; h++) {
        __nv_bfloat16* cur = sm + (h & 1) * BUFSET;
        __nv_bfloat16* nxt = sm + ((h + 1) & 1) * BUFSET;
        bool pf = (h + 1 < nhalf);
        if (pf) {
            fill_B_async(Bhi, Blo, nxt + 2 * TILEH, nxt + 3 * TILEH,
                         n0, (h + 1) << 5, KPAD, tid);
            cp_commit();
            load_A_regs<CONCAT>(va, A, A2, m0, (h + 1) << 5, M, K, K1, tid);
        }

        int rem = K - (h << 5);
        int ksteps = (rem + 15) >> 4;
        if (ksteps > 2) ksteps = 2;
        if (jp_max == 4)
            mma_phase<4>(acc, cur, cur + TILEH, cur + 2 * TILEH, cur + 3 * TILEH,
                         ksteps, warp_m, warp_n, a_row_l, a_kh, b_mat, b_rr);
        else if (jp_max == 3)
            mma_phase<3>(acc, cur, cur + TILEH, cur + 2 * TILEH, cur + 3 * TILEH,
                         ksteps, warp_m, warp_n, a_row_l, a_kh, b_mat, b_rr);

        if (pf) {
            store_A_split(va, nxt, nxt + TILEH, tid);
            cp_wait0();
        }
        __syncthreads();
    }

    // ---- epilogue: bias (+resid) + relu ----
    int tq = lid >> 2;
    int tr = lid & 3;
    int row_base = m0 + warp_m * 32 + tq;
    int col_base = n0 + warp_n * 64 + tr * 2;
#pragma unroll
    for (int i = 0; i < 2; i++) {
#pragma unroll
        for (int j = 0; j < 8; j++) {
            int col = col_base + j * 8;
            if (col >= Nn) continue;
            float2 bs = *reinterpret_cast<const float2*>(bias + col);
#pragma unroll
            for (int half = 0; half < 2; half++) {
                int row = row_base + i * 16 + half * 8;
                if (row >= M) continue;
                float v0 = acc[i][j][2*half + 0] + bs.x;
                float v1 = acc[i][j][2*half + 1] + bs.y;
                if (RESID) {
                    float2 rr = *reinterpret_cast<const float2*>(resid + (size_t)row * Nn + col);
                    v0 += rr.x; v1 += rr.y;
                }
                float2 o;
                o.x = fmaxf(v0, 0.f);
                o.y = fmaxf(v1, 0.f);
                *reinterpret_cast<float2*>(C + (size_t)row * Nn + col) = o;
            }
        }
    }
}

// ------- per-node CSR aggregation: warp-per-node, barrier-free, high MLP -----
// lane q-dims: lane + 32q (q<9), lane+288 (lane<12). 10 independent loads/edge.
__global__ __launch_bounds__(256)
void aggregate_kernel(const float* __restrict__ h0,
                      const int* __restrict__ rowptr,
                      const int* __restrict__ cnt_arr,
                      const int4* __restrict__ edges,
                      float* __restrict__ agg) {
    int node = blockIdx.x * 8 + (threadIdx.x >> 5);
    if (node >= NN) return;
    int lane = threadIdx.x & 31;
    int start = rowptr[node];
    int cnt = cnt_arr[node];

    float acc[10];
#pragma unroll
    for (int q = 0; q < 10; q++) acc[q] = 0.f;

    for (int j = 0; j < cnt; j++) {
        int4 ed = __ldg(&edges[start + j]);            // same addr warp-wide -> broadcast
        float w = __int_as_float(ed.z);
        const float* row = h0 + (size_t)ed.x * HID;
#pragma unroll
        for (int q = 0; q < 9; q++) acc[q] += w * __ldg(row + lane + 32 * q);
        if (lane < 12) acc[9] += w * __ldg(row + lane + 288);
    }

    float inv = 1.0f / fmaxf((float)cnt, 1.0f);
    float* out = agg + (size_t)node * HID;
#pragma unroll
    for (int q = 0; q < 9; q++) out[lane + 32 * q] = acc[q] * inv;
    if (lane < 12) out[lane + 288] = acc[9] * inv;
}

// ---------------- launch ----------------
extern "C" void kernel_launch(void* const* d_in, const int* in_sizes, int n_in,
                              void* d_out, int out_size) {
    const float* x = nullptr;
    const float* edge_attr = nullptr;
    const float* edge_weight = nullptr;
    const float* W0 = nullptr;
    const float* b0 = nullptr;
    const float* W  = nullptr;
    const float* b  = nullptr;
    const int*   edge_index = nullptr;

    for (int i = 0; i < n_in; i++) {
        int s = in_sizes[i];
        switch (s) {
            case NN * NODE_D:      x = (const float*)d_in[i]; break;
            case EE * EDGE_D:      edge_attr = (const float*)d_in[i]; break;
            case EE:               edge_weight = (const float*)d_in[i]; break;
            case (NODE_D + EDGE_D) * HID: W0 = (const float*)d_in[i]; break;
            case HID * HID:        W = (const float*)d_in[i]; break;
            case 2 * EE:           edge_index = (const int*)d_in[i]; break;
            case HID:
                if (!b0) b0 = (const float*)d_in[i];
                else     b  = (const float*)d_in[i];
                break;
            default: break; // node_weight unused
        }
    }
    if (!b) b = b0;

    void *p_inc, *p_agg, *p_h0, *p_cnt, *p_rowptr, *p_cursor, *p_edges;
    void *p_w0h, *p_w0l, *p_wh, *p_wl;
    cudaGetSymbolAddress(&p_inc,    g_inc);
    cudaGetSymbolAddress(&p_agg,    g_agg);
    cudaGetSymbolAddress(&p_h0,     g_h0);
    cudaGetSymbolAddress(&p_cnt,    g_cnt);
    cudaGetSymbolAddress(&p_rowptr, g_rowptr);
    cudaGetSymbolAddress(&p_cursor, g_cursor);
    cudaGetSymbolAddress(&p_edges,  g_edges);
    cudaGetSymbolAddress(&p_w0h,    g_w0t_hi);
    cudaGetSymbolAddress(&p_w0l,    g_w0t_lo);
    cudaGetSymbolAddress(&p_wh,     g_wt_hi);
    cudaGetSymbolAddress(&p_wl,     g_wt_lo);

    float* inc     = (float*)p_inc;
    float* agg     = (float*)p_agg;
    int*   cnt     = (int*)p_cnt;
    int*   rowptr  = (int*)p_rowptr;
    int*   cursor  = (int*)p_cursor;
    int4*  edges   = (int4*)p_edges;

    float* h = (float*)d_out;
    float* h0 = (out_size >= 2 * NN * HID) ? (float*)d_out + (size_t)NN * HID
                                           : (float*)p_h0;

    cudaFuncSetAttribute(gemm_hmma<true,  false>,
                         cudaFuncAttributeMaxDynamicSharedMemorySize, GEMM_SMEM);
    cudaFuncSetAttribute(gemm_hmma<false, true>,
                         cudaFuncAttributeMaxDynamicSharedMemorySize, GEMM_SMEM);

    // 1. fused: zero cnt + weight prep
    fused_prep_kernel<<<(PREP_TOTAL + 255) / 256, 256>>>(
        W0, W, cnt,
        (__nv_bfloat16*)p_w0h, (__nv_bfloat16*)p_w0l,
        (__nv_bfloat16*)p_wh,  (__nv_bfloat16*)p_wl);

    // 2. dst histogram
    hist_kernel<<<(EE + 255) / 256, 256>>>(edge_index, cnt);

    // 3. scan -> rowptr/cursor
    scan_kernel<<<1, 1024>>>(cnt, rowptr, cursor);

    // 4. bucket edges (packed)
    fill_kernel<<<(EE + 255) / 256, 256>>>(edge_weight, edge_index, cursor, edges);

    // 5. inc via CSR gather (no atomics)
    inc_csr_kernel<<<(NN + 7) / 8, 256>>>(edge_attr, rowptr, cnt, edges, inc);

    // 6. GEMM1: h0 = relu([x | inc] @ W0 + b0)
    {
        dim3 grid(NPAD / 128, (NN + 127) / 128);
        gemm_hmma<true, false><<<grid, 256, GEMM_SMEM>>>(
            x, inc, (__nv_bfloat16*)p_w0h, (__nv_bfloat16*)p_w0l,
            b0, nullptr, h0, NN, HID, NODE_D + EDGE_D, NODE_D, K1PAD);
    }

    // 7. aggregation: agg = scatter_mean(edge_weight * h0[src], dst)
    aggregate_kernel<<<(NN + 7) / 8, 256>>>(h0, rowptr, cnt, edges, agg);

    // 8. GEMM2: h = relu(h0 + agg @ W + b)
    {
        dim3 grid(NPAD / 128, (NN + 127) / 128);
        gemm_hmma<false, true><<<grid, 256, GEMM_SMEM>>>(
            agg, nullptr, (__nv_bfloat16*)p_wh, (__nv_bfloat16*)p_wl,
            b, h0, h, NN, HID, HID, 0, K2PAD);
    }
}